// round 4
// baseline (speedup 1.0000x reference)
#include <cuda_runtime.h>
#include <math.h>
#include <stdint.h>

// ---------------------------------------------------------------------------
// CoPE, f32x2 FMA + warp-autonomous reduction/softmax:
//   inv_n = 1/max(||pos_n||, eps)
//   logits = (q @ pos^T) * inv_n / sqrt(D); gates = softmax(logits)
//   out = (gates * inv_n) @ pos
// B=4, T=4096, D=4096, N=16.
// ---------------------------------------------------------------------------

typedef unsigned long long ull;

#define DIM        4096
#define DIM4       1024               // float4 per row
#define NPOS       16
#define ROWS_TOT   16384
#define ROWS_BLK   16                 // rows per CTA (8 warps x 2 rows)
#define NBLOCKS    (ROWS_TOT / ROWS_BLK)   // 1024
#define NTHREADS   256
#define CHUNK_F4   128                // float4 of D per n-row per chunk
#define NCHUNKS    8

#define BUF_FLOATS (NPOS * CHUNK_F4 * 4)   // 8192 floats = 32KB per buffer
#define SMEM_FLOATS (2 * BUF_FLOATS)
#define SMEM_BYTES  (SMEM_FLOATS * 4)      // 64KB -> 2 CTAs/SM

__device__ float g_inv[NPOS];

// ---------------------------------------------------------------------------
__global__ void cope_inv_kernel(const float* __restrict__ pos)
{
    const int n   = blockIdx.x;
    const int tid = threadIdx.x;
    const float* row = pos + n * DIM;

    float s = 0.f;
    #pragma unroll 4
    for (int i = tid; i < DIM; i += 256) {
        float v = row[i];
        s = fmaf(v, v, s);
    }
    #pragma unroll
    for (int o = 16; o > 0; o >>= 1) s += __shfl_down_sync(0xffffffffu, s, o);

    __shared__ float sred[8];
    if ((tid & 31) == 0) sred[tid >> 5] = s;
    __syncthreads();
    if (tid == 0) {
        float t = 0.f;
        #pragma unroll
        for (int w = 0; w < 8; w++) t += sred[w];
        g_inv[n] = 1.0f / fmaxf(sqrtf(t), 1e-12f);
    }
}

// ---------------------------------------------------------------------------
__device__ __forceinline__ ull ffma2(ull a, ull b, ull c)
{
    ull d;
    asm("fma.rn.f32x2 %0, %1, %2, %3;" : "=l"(d) : "l"(a), "l"(b), "l"(c));
    return d;
}
__device__ __forceinline__ ull pack2(float lo, float hi)
{
    ull d;
    asm("mov.b64 %0, {%1, %2};" : "=l"(d) : "f"(lo), "f"(hi));
    return d;
}
__device__ __forceinline__ float lo2(ull a) { return __uint_as_float((unsigned)(a & 0xffffffffu)); }
__device__ __forceinline__ float hi2(ull a) { return __uint_as_float((unsigned)(a >> 32)); }

__device__ __forceinline__ void cp_async16(void* s, const void* g)
{
    uint32_t saddr = (uint32_t)__cvta_generic_to_shared(s);
    asm volatile("cp.async.cg.shared.global [%0], [%1], 16;\n"
                 :: "r"(saddr), "l"(g));
}
__device__ __forceinline__ void cp_commit()
{
    asm volatile("cp.async.commit_group;\n" ::);
}
__device__ __forceinline__ void cp_wait1()
{
    asm volatile("cp.async.wait_group 1;\n" ::);
}
__device__ __forceinline__ void cp_wait0()
{
    asm volatile("cp.async.wait_group 0;\n" ::);
}

// stage one [16][512]-float chunk of raw pos (async); 8 float4 per thread
__device__ __forceinline__ void stage_chunk(float4* buf, const float4* gp4,
                                            int c, int tid)
{
    #pragma unroll
    for (int i = 0; i < 8; i++) {
        int idx = tid + i * NTHREADS;        // 0..2047
        int n   = idx >> 7;                  // /128
        int d4  = idx & 127;
        cp_async16(buf + n * CHUNK_F4 + d4,
                   gp4 + (size_t)n * DIM4 + (size_t)c * CHUNK_F4 + d4);
    }
}

// ---------------------------------------------------------------------------
__global__ void __launch_bounds__(NTHREADS, 2)
cope_main_kernel(const float* __restrict__ q, const float* __restrict__ pos,
                 float* __restrict__ out)
{
    extern __shared__ float smem[];
    float4* buf0 = (float4*)smem;
    float4* buf1 = (float4*)(smem + BUF_FLOATS);

    const int tid  = threadIdx.x;
    const int wid  = tid >> 5;               // 0..7 (2 rows each)
    const int lane = tid & 31;
    const int row0 = blockIdx.x * ROWS_BLK + wid * 2;

    const ulonglong2* qq  = (const ulonglong2*)q;
    const float4*     gp4 = (const float4*)pos;
    ulonglong2*       oo  = (ulonglong2*)out;

    // prologue: stage chunks 0,1
    stage_chunk(buf0, gp4, 0, tid); cp_commit();
    stage_chunk(buf1, gp4, 1, tid); cp_commit();

    // ------------------------- pass 1: logits ----------------------------
    ull acc[2][16];
    #pragma unroll
    for (int r = 0; r < 2; r++)
        #pragma unroll
        for (int n = 0; n < NPOS; n++) acc[r][n] = 0ull;

    for (int c = 0; c < NCHUNKS; c++) {
        if (c < NCHUNKS - 1) cp_wait1(); else cp_wait0();
        __syncthreads();

        const ulonglong2* sp = (const ulonglong2*)((c & 1) ? buf1 : buf0);

        #pragma unroll
        for (int j = 0; j < 4; j++) {
            const int d4 = lane + j * 32;
            ulonglong2 qv[2];
            #pragma unroll
            for (int r = 0; r < 2; r++)
                qv[r] = qq[(size_t)(row0 + r) * DIM4 + (size_t)c * CHUNK_F4 + d4];

            #pragma unroll
            for (int n = 0; n < NPOS; n++) {
                const ulonglong2 p = sp[n * CHUNK_F4 + d4];
                #pragma unroll
                for (int r = 0; r < 2; r++) {
                    ull a = acc[r][n];
                    a = ffma2(qv[r].x, p.x, a);
                    a = ffma2(qv[r].y, p.y, a);
                    acc[r][n] = a;
                }
            }
        }
        __syncthreads();
        if (c + 2 < NCHUNKS) {
            stage_chunk((c & 1) ? buf1 : buf0, gp4, c + 2, tid);
            cp_commit();
        }
    }
    // buffers now hold: buf0 = chunk 6, buf1 = chunk 7

    // -------- warp-local transpose-reduce: lane l -> sum for (r,n)=l ------
    float v[32];
    #pragma unroll
    for (int r = 0; r < 2; r++)
        #pragma unroll
        for (int n = 0; n < NPOS; n++)
            v[r * 16 + n] = lo2(acc[r][n]) + hi2(acc[r][n]);

    #pragma unroll
    for (int m = 1; m < 32; m <<= 1) {
        #pragma unroll
        for (int j = 0; j < 32; j++) {
            float o = __shfl_xor_sync(0xffffffffu, v[j], m);
            if ((j & m) == (lane & m)) v[j] += o;
        }
    }
    // lane l holds raw dot for row (l>>4), code n=(l&15)
    const float invn  = __ldg(&g_inv[lane & 15]);
    float logit = v[lane] * 0.015625f * invn;     // * 1/sqrt(4096) * inv_norm

    // ---------------- in-warp softmax over each 16-lane group -------------
    float mx = logit;
    #pragma unroll
    for (int o = 8; o > 0; o >>= 1)
        mx = fmaxf(mx, __shfl_xor_sync(0xffffffffu, mx, o));
    float e = expf(logit - mx);
    float sum = e;
    #pragma unroll
    for (int o = 8; o > 0; o >>= 1)
        sum += __shfl_xor_sync(0xffffffffu, sum, o);
    const float g = e * (1.0f / sum) * invn;      // fold inv_norm into gate

    // gather all 32 gates (2 rows x 16 n), packed for f32x2
    ull gt[2][16];
    #pragma unroll
    for (int r = 0; r < 2; r++)
        #pragma unroll
        for (int n = 0; n < NPOS; n++) {
            float gj = __shfl_sync(0xffffffffu, g, r * 16 + n);
            gt[r][n] = pack2(gj, gj);
        }

    // -------------------------- pass 2: output ---------------------------
    // reverse chunk order: chunks 7 (buf1) and 6 (buf0) already resident
    for (int cc = 0; cc < NCHUNKS; cc++) {
        const int c = NCHUNKS - 1 - cc;
        if (c <= NCHUNKS - 3) {
            if (c > 0) cp_wait1(); else cp_wait0();
        }
        __syncthreads();

        const ulonglong2* sp = (const ulonglong2*)((c & 1) ? buf1 : buf0);

        #pragma unroll
        for (int j = 0; j < 4; j++) {
            const int d4 = lane + j * 32;
            ulonglong2 o[2];
            #pragma unroll
            for (int r = 0; r < 2; r++) { o[r].x = 0ull; o[r].y = 0ull; }

            #pragma unroll
            for (int n = 0; n < NPOS; n++) {
                const ulonglong2 p = sp[n * CHUNK_F4 + d4];
                #pragma unroll
                for (int r = 0; r < 2; r++) {
                    o[r].x = ffma2(gt[r][n], p.x, o[r].x);
                    o[r].y = ffma2(gt[r][n], p.y, o[r].y);
                }
            }
            #pragma unroll
            for (int r = 0; r < 2; r++)
                oo[(size_t)(row0 + r) * DIM4 + (size_t)c * CHUNK_F4 + d4] = o[r];
        }
        __syncthreads();
        if (c >= 2) {
            stage_chunk((c & 1) ? buf1 : buf0, gp4, c - 2, tid);
            cp_commit();
        }
    }
}

// ---------------------------------------------------------------------------
extern "C" void kernel_launch(void* const* d_in, const int* in_sizes, int n_in,
                              void* d_out, int out_size)
{
    const float* q   = (const float*)d_in[0];
    // d_in[1] = x : unused by the reference computation
    const float* pos = (const float*)d_in[2];
    float* out = (float*)d_out;

    cudaFuncSetAttribute(cope_main_kernel,
                         cudaFuncAttributeMaxDynamicSharedMemorySize, SMEM_BYTES);

    cope_inv_kernel<<<NPOS, 256>>>(pos);
    cope_main_kernel<<<NBLOCKS, NTHREADS, SMEM_BYTES>>>(q, pos, out);
}

// round 5
// speedup vs baseline: 1.1944x; 1.1944x over previous
#include <cuda_runtime.h>
#include <math.h>
#include <stdint.h>

// ---------------------------------------------------------------------------
// CoPE, f32x2 FMA, 4-row tile, register-butterfly reduction (no smem scratch):
//   inv_n = 1/max(||pos_n||, eps)
//   logits = (q @ pos^T) * inv_n / sqrt(D); gates = softmax(logits)
//   out = (gates * inv_n) @ pos
// B=4, T=4096, D=4096, N=16.
// ---------------------------------------------------------------------------

typedef unsigned long long ull;

#define DIM        4096
#define DIM4       1024               // float4 per row
#define NPOS       16
#define ROWS_TOT   16384
#define ROWS_BLK   16                 // rows per CTA (4 warps x 4 rows)
#define NBLOCKS    (ROWS_TOT / ROWS_BLK)   // 1024
#define NTHREADS   128
#define CHUNK_F4   128                // float4 of D per n-row per chunk
#define NCHUNKS    8

#define BUF_FLOATS (NPOS * CHUNK_F4 * 4)   // 8192 floats = 32KB per buffer
#define SMEM_BYTES (2 * BUF_FLOATS * 4)    // 64KB -> 3 CTAs/SM

__device__ float g_inv[NPOS];

// ---------------------------------------------------------------------------
__global__ void cope_inv_kernel(const float* __restrict__ pos)
{
    const int n   = blockIdx.x;
    const int tid = threadIdx.x;
    const float* row = pos + n * DIM;

    float s = 0.f;
    #pragma unroll 4
    for (int i = tid; i < DIM; i += 256) {
        float v = row[i];
        s = fmaf(v, v, s);
    }
    #pragma unroll
    for (int o = 16; o > 0; o >>= 1) s += __shfl_down_sync(0xffffffffu, s, o);

    __shared__ float sred[8];
    if ((tid & 31) == 0) sred[tid >> 5] = s;
    __syncthreads();
    if (tid == 0) {
        float t = 0.f;
        #pragma unroll
        for (int w = 0; w < 8; w++) t += sred[w];
        g_inv[n] = 1.0f / fmaxf(sqrtf(t), 1e-12f);
    }
}

// ---------------------------------------------------------------------------
__device__ __forceinline__ ull ffma2(ull a, ull b, ull c)
{
    ull d;
    asm("fma.rn.f32x2 %0, %1, %2, %3;" : "=l"(d) : "l"(a), "l"(b), "l"(c));
    return d;
}
__device__ __forceinline__ ull pack2(float lo, float hi)
{
    ull d;
    asm("mov.b64 %0, {%1, %2};" : "=l"(d) : "f"(lo), "f"(hi));
    return d;
}
__device__ __forceinline__ float lo2(ull a) { return __uint_as_float((unsigned)(a & 0xffffffffu)); }
__device__ __forceinline__ float hi2(ull a) { return __uint_as_float((unsigned)(a >> 32)); }

__device__ __forceinline__ void cp_async16(void* s, const void* g)
{
    uint32_t saddr = (uint32_t)__cvta_generic_to_shared(s);
    asm volatile("cp.async.cg.shared.global [%0], [%1], 16;\n"
                 :: "r"(saddr), "l"(g));
}
__device__ __forceinline__ void cp_commit()
{
    asm volatile("cp.async.commit_group;\n" ::);
}
__device__ __forceinline__ void cp_wait1()
{
    asm volatile("cp.async.wait_group 1;\n" ::);
}
__device__ __forceinline__ void cp_wait0()
{
    asm volatile("cp.async.wait_group 0;\n" ::);
}

// stage one [16][512]-float chunk of raw pos (async); 16 float4 per thread
__device__ __forceinline__ void stage_chunk(float4* buf, const float4* gp4,
                                            int c, int tid)
{
    #pragma unroll
    for (int i = 0; i < 16; i++) {
        int idx = tid + i * NTHREADS;        // 0..2047
        int n   = idx >> 7;                  // /128
        int d4  = idx & 127;
        cp_async16(buf + n * CHUNK_F4 + d4,
                   gp4 + (size_t)n * DIM4 + (size_t)c * CHUNK_F4 + d4);
    }
}

// ---------------------------------------------------------------------------
__global__ void __launch_bounds__(NTHREADS, 3)
cope_main_kernel(const float* __restrict__ q, const float* __restrict__ pos,
                 float* __restrict__ out)
{
    extern __shared__ float smem[];
    float4* buf0 = (float4*)smem;
    float4* buf1 = (float4*)(smem + BUF_FLOATS);

    const int tid  = threadIdx.x;
    const int wid  = tid >> 5;               // 0..3 (4 rows each)
    const int lane = tid & 31;
    const int row0 = blockIdx.x * ROWS_BLK + wid * 4;

    const ulonglong2* qq  = (const ulonglong2*)q;
    const float4*     gp4 = (const float4*)pos;
    ulonglong2*       oo  = (ulonglong2*)out;

    // prologue: stage chunks 0,1
    stage_chunk(buf0, gp4, 0, tid); cp_commit();
    stage_chunk(buf1, gp4, 1, tid); cp_commit();

    // ------------------------- pass 1: logits ----------------------------
    ull acc[4][16];
    #pragma unroll
    for (int r = 0; r < 4; r++)
        #pragma unroll
        for (int n = 0; n < NPOS; n++) acc[r][n] = 0ull;

    for (int c = 0; c < NCHUNKS; c++) {
        if (c < NCHUNKS - 1) cp_wait1(); else cp_wait0();
        __syncthreads();

        const ulonglong2* sp = (const ulonglong2*)((c & 1) ? buf1 : buf0);

        #pragma unroll
        for (int j = 0; j < 4; j++) {
            const int d4 = lane + j * 32;
            ulonglong2 qv[4];
            #pragma unroll
            for (int r = 0; r < 4; r++)
                qv[r] = qq[(size_t)(row0 + r) * DIM4 + (size_t)c * CHUNK_F4 + d4];

            #pragma unroll
            for (int n = 0; n < NPOS; n++) {
                const ulonglong2 p = sp[n * CHUNK_F4 + d4];
                #pragma unroll
                for (int r = 0; r < 4; r++) {
                    ull a = acc[r][n];
                    a = ffma2(qv[r].x, p.x, a);
                    a = ffma2(qv[r].y, p.y, a);
                    acc[r][n] = a;
                }
            }
        }
        __syncthreads();
        if (c + 2 < NCHUNKS) {
            stage_chunk((c & 1) ? buf1 : buf0, gp4, c + 2, tid);
            cp_commit();
        }
    }
    // buffers now hold: buf0 = chunk 6, buf1 = chunk 7

    // ------- register butterfly transpose-reduce over the 32 d-lanes ------
    // element j = r*16+n (j<64). After 5 halving steps, lane l holds:
    //   w[0] = dot(row l>>4,     n = l&15)
    //   w[1] = dot(row 2+(l>>4), n = l&15)
    float w[64];
    #pragma unroll
    for (int r = 0; r < 4; r++)
        #pragma unroll
        for (int n = 0; n < NPOS; n++)
            w[r * 16 + n] = lo2(acc[r][n]) + hi2(acc[r][n]);

#define RED_STEP(m, L)                                              \
    _Pragma("unroll")                                               \
    for (int t = 0; t < (L); t++) {                                 \
        float a_  = w[2 * t], b_ = w[2 * t + 1];                    \
        float ao_ = __shfl_xor_sync(0xffffffffu, a_, (m));          \
        float bo_ = __shfl_xor_sync(0xffffffffu, b_, (m));          \
        w[t] = (lane & (m)) ? (b_ + bo_) : (a_ + ao_);              \
    }
    RED_STEP(1, 32)
    RED_STEP(2, 16)
    RED_STEP(4, 8)
    RED_STEP(8, 4)
    RED_STEP(16, 2)
#undef RED_STEP

    const float invn = __ldg(&g_inv[lane & 15]);
    float lgA = w[0] * 0.015625f * invn;       // row rA = lane>>4
    float lgB = w[1] * 0.015625f * invn;       // row rB = 2 + (lane>>4)

    // -------- in-warp softmax over each 16-lane n-group (both rows) -------
    float mA = lgA, mB = lgB;
    #pragma unroll
    for (int o = 8; o > 0; o >>= 1) {
        mA = fmaxf(mA, __shfl_xor_sync(0xffffffffu, mA, o));
        mB = fmaxf(mB, __shfl_xor_sync(0xffffffffu, mB, o));
    }
    float eA = expf(lgA - mA), eB = expf(lgB - mB);
    float sA = eA, sB = eB;
    #pragma unroll
    for (int o = 8; o > 0; o >>= 1) {
        sA += __shfl_xor_sync(0xffffffffu, sA, o);
        sB += __shfl_xor_sync(0xffffffffu, sB, o);
    }
    const float gA = eA * (1.0f / sA) * invn;  // fold inv_norm into gate
    const float gB = eB * (1.0f / sB) * invn;

    // gather gates for this thread's 4 rows, packed for f32x2
    ull gt[4][16];
    #pragma unroll
    for (int n = 0; n < NPOS; n++) {
        #pragma unroll
        for (int r = 0; r < 2; r++) {
            float gj = __shfl_sync(0xffffffffu, gA, (r << 4) | n);
            gt[r][n] = pack2(gj, gj);
        }
        #pragma unroll
        for (int r = 2; r < 4; r++) {
            float gj = __shfl_sync(0xffffffffu, gB, ((r - 2) << 4) | n);
            gt[r][n] = pack2(gj, gj);
        }
    }

    // -------------------------- pass 2: output ---------------------------
    // reverse chunk order: chunks 7 (buf1) and 6 (buf0) already resident
    for (int cc = 0; cc < NCHUNKS; cc++) {
        const int c = NCHUNKS - 1 - cc;
        if (c <= NCHUNKS - 3) {
            if (c > 0) cp_wait1(); else cp_wait0();
        }
        __syncthreads();

        const ulonglong2* sp = (const ulonglong2*)((c & 1) ? buf1 : buf0);

        #pragma unroll
        for (int j = 0; j < 4; j++) {
            const int d4 = lane + j * 32;
            ulonglong2 o[4];
            #pragma unroll
            for (int r = 0; r < 4; r++) { o[r].x = 0ull; o[r].y = 0ull; }

            #pragma unroll
            for (int n = 0; n < NPOS; n++) {
                const ulonglong2 p = sp[n * CHUNK_F4 + d4];
                #pragma unroll
                for (int r = 0; r < 4; r++) {
                    o[r].x = ffma2(gt[r][n], p.x, o[r].x);
                    o[r].y = ffma2(gt[r][n], p.y, o[r].y);
                }
            }
            #pragma unroll
            for (int r = 0; r < 4; r++)
                oo[(size_t)(row0 + r) * DIM4 + (size_t)c * CHUNK_F4 + d4] = o[r];
        }
        __syncthreads();
        if (c >= 2) {
            stage_chunk((c & 1) ? buf1 : buf0, gp4, c - 2, tid);
            cp_commit();
        }
    }
}

// ---------------------------------------------------------------------------
extern "C" void kernel_launch(void* const* d_in, const int* in_sizes, int n_in,
                              void* d_out, int out_size)
{
    const float* q   = (const float*)d_in[0];
    // d_in[1] = x : unused by the reference computation
    const float* pos = (const float*)d_in[2];
    float* out = (float*)d_out;

    cudaFuncSetAttribute(cope_main_kernel,
                         cudaFuncAttributeMaxDynamicSharedMemorySize, SMEM_BYTES);

    cope_inv_kernel<<<NPOS, 256>>>(pos);
    cope_main_kernel<<<NBLOCKS, NTHREADS, SMEM_BYTES>>>(q, pos, out);
}